// round 14
// baseline (speedup 1.0000x reference)
#include <cuda_runtime.h>
#include <cstdint>

#define XH 130
#define XW 130
#define XC 64
#define NPIX (XH * XW)
#define NRED 16
#define NSPAN 196
#define NLAYERS 6
#define TILE 8
#define TS 14
#define NTB 17

// ---------------- scratch ----------------
__device__ float g_bufA[NPIX * XC];
__device__ float g_bufB[NPIX * XC];
__device__ float g_redT[NLAYERS][16 * 16 * 4];   // [q][r] float4 (gamma-folded)

// ---------------- f32x2 helpers ----------------
__device__ __forceinline__ unsigned long long dup2(float k) {
    unsigned long long r;
    asm("mov.b64 %0, {%1, %1};" : "=l"(r) : "f"(k));
    return r;
}
__device__ __forceinline__ unsigned long long pack2f(float2 v) {
    unsigned long long r;
    asm("mov.b64 %0, {%1, %2};" : "=l"(r) : "f"(v.x), "f"(v.y));
    return r;
}
__device__ __forceinline__ unsigned long long fma2(unsigned long long a,
                                                   unsigned long long b,
                                                   unsigned long long c) {
    unsigned long long d;
    asm("fma.rn.f32x2 %0, %1, %2, %3;" : "=l"(d) : "l"(a), "l"(b), "l"(c));
    return d;
}
__device__ __forceinline__ float2 unpack2(unsigned long long v) {
    float2 r;
    asm("mov.b64 {%0, %1}, %2;" : "=f"(r.x), "=f"(r.y) : "l"(v));
    return r;
}

// ---------------- PDL helpers ----------------
__device__ __forceinline__ void pdl_wait() {
    asm volatile("griddepcontrol.wait;" ::: "memory");
}
__device__ __forceinline__ void pdl_trigger() {
    asm volatile("griddepcontrol.launch_dependents;" ::: "memory");
}

// ---------------- async-bulk helpers ----------------
__device__ __forceinline__ uint32_t smem_u32(const void* p) {
    uint32_t a;
    asm("{ .reg .u64 t; cvta.to.shared.u64 t, %1; cvt.u32.u64 %0, t; }"
        : "=r"(a) : "l"(p));
    return a;
}
__device__ __forceinline__ void mbar_init(uint32_t addr, uint32_t cnt) {
    asm volatile("mbarrier.init.shared.b64 [%0], %1;" :: "r"(addr), "r"(cnt) : "memory");
}
__device__ __forceinline__ void mbar_expect_tx(uint32_t addr, uint32_t bytes) {
    asm volatile("mbarrier.arrive.expect_tx.shared.b64 _, [%0], %1;"
                 :: "r"(addr), "r"(bytes) : "memory");
}
__device__ __forceinline__ void bulk_g2s(uint32_t dst, const void* src,
                                         uint32_t bytes, uint32_t mbar) {
    asm volatile("cp.async.bulk.shared::cta.global.mbarrier::complete_tx::bytes "
                 "[%0], [%1], %2, [%3];"
                 :: "r"(dst), "l"(src), "r"(bytes), "r"(mbar) : "memory");
}
__device__ __forceinline__ void mbar_wait(uint32_t addr, uint32_t parity) {
    asm volatile(
        "{\n\t.reg .pred P;\n\t"
        "W_%=:\n\t"
        "mbarrier.try_wait.parity.acquire.cta.shared::cta.b64 P, [%0], %1, 0x989680;\n\t"
        "@P bra.uni D_%=;\n\t"
        "bra.uni W_%=;\n\t"
        "D_%=:\n\t}"
        :: "r"(addr), "r"(parity) : "memory");
}

// ---------------- conv_in: tiled (8x8 px/block), weights in registers ----------------
__global__ void conv_in_kernel(const float* __restrict__ in,
                               const float* __restrict__ w,
                               const float* __restrict__ b,
                               const float* __restrict__ red_w,
                               const float* __restrict__ gamma,
                               float* __restrict__ out) {
    if (blockIdx.x >= NTB * NTB) {
        int idx = (blockIdx.x - NTB * NTB) * 256 + threadIdx.x;   // 0..6143
        int l = idx >> 10, rem = idx & 1023;
        int r = rem >> 6, c = rem & 63;
        g_redT[l][((c >> 2) * 16 + r) * 4 + (c & 3)] =
            gamma[l * 16 + r] * red_w[(l * 16 + r) * 64 + c];
        pdl_trigger();
        return;
    }
    __shared__ float ws[27 * 64];
    __shared__ float xt[3 * 10 * 10];
    int tid = threadIdx.x, lane = tid & 31, wp = tid >> 5;
    int by = blockIdx.x / NTB, bx = blockIdx.x % NTB;
    int y0 = by * TILE, x0 = bx * TILE;

    for (int i = tid; i < 27 * 64; i += 256) {
        int t = i >> 6, c = i & 63;
        ws[t * 64 + c] = w[c * 27 + t];
    }
    for (int i = tid; i < 300; i += 256) {
        int ic = i / 100, rem = i % 100;
        int rr = rem / 10, cc = rem % 10;
        int gy = y0 - 2 + rr, gx = x0 - 2 + cc;
        float v = 0.f;
        if (gy >= 0 && gy < 128 && gx >= 0 && gx < 128)
            v = in[(ic * 128 + gy) * 128 + gx];
        xt[i] = v;
    }
    __syncthreads();

    int c0 = lane * 2;
    unsigned long long wv[27];
#pragma unroll
    for (int t = 0; t < 27; t++)
        wv[t] = pack2f(*(const float2*)&ws[t * 64 + c0]);
    unsigned long long bv = pack2f(make_float2(b[c0], b[c0 + 1]));

#pragma unroll
    for (int k = 0; k < 8; k++) {
        int pp = wp * 8 + k;
        int py = pp >> 3, px = pp & 7;
        int gy = y0 + py, gx = x0 + px;
        unsigned long long acc = bv;
#pragma unroll
        for (int ic = 0; ic < 3; ic++)
#pragma unroll
            for (int ky = 0; ky < 3; ky++)
#pragma unroll
                for (int kx = 0; kx < 3; kx++) {
                    float xv = xt[(ic * 10 + (py + ky)) * 10 + (px + kx)];
                    acc = fma2(wv[ic * 9 + ky * 3 + kx], dup2(xv), acc);
                }
        if (gy < XH && gx < XW) {
            float2 o = unpack2(acc);
            *(float2*)&out[(gy * XW + gx) * XC + c0] = o;
        }
    }
    pdl_trigger();
}

// ---------------- fused involution layer ----------------
#define SM_XS   0
#define SM_SKER (TS * TS * XC)                // 12544
#define SM_T2   (SM_SKER + 64 * 224)          // 26880
#define SM_BETA (SM_T2 + 1024)                // 27904
#define SM_MBAR (SM_BETA + 16)                // 27920 (8B aligned)
#define SM_TOT  (SM_MBAR + 2)                 // 27922 floats = 111,688 B

__global__ void __launch_bounds__(512, 2)
inv_kernel(const float* __restrict__ xin, float* __restrict__ xout,
           const float* __restrict__ redT4, const float* __restrict__ beta,
           const float* __restrict__ span_w, const float* __restrict__ span_b) {
    extern __shared__ float sm[];
    float* xs     = sm + SM_XS;
    float* sker   = sm + SM_SKER;
    float* redT_s = sker;            // alias: read in T phase, overwritten in K phase
    float* t2_s   = sm + SM_T2;
    float* beta_s = sm + SM_BETA;

    int tid = threadIdx.x, lane = tid & 31, w = tid >> 5;
    int by = blockIdx.x / NTB, bx = blockIdx.x % NTB;
    int y0 = by * TILE - 3, x0 = bx * TILE - 3;

    uint32_t smem_base = smem_u32(sm);
    uint32_t mbar = smem_base + SM_MBAR * 4;

    // ---- PDL prologue: span weights (pure inputs) ----
    float wr1[16], wr2[16], sb1 = 0.f, sb2 = 0.f;
    int goff1 = 0, goff2 = 0;
    int kpbase = (w >> 2) * 8;
    bool j2ok;
    {
        int j1 = (w & 3) * 32 + lane;
        int j2 = j1 + 128;
        j2ok = (j2 < NSPAN);
#pragma unroll
        for (int q = 0; q < 4; q++) {
            float4 v = *(const float4*)&span_w[j1 * 16 + q * 4];
            wr1[q * 4] = v.x; wr1[q * 4 + 1] = v.y; wr1[q * 4 + 2] = v.z; wr1[q * 4 + 3] = v.w;
            float4 u = make_float4(0.f, 0.f, 0.f, 0.f);
            if (j2ok) u = *(const float4*)&span_w[j2 * 16 + q * 4];
            wr2[q * 4] = u.x; wr2[q * 4 + 1] = u.y; wr2[q * 4 + 2] = u.z; wr2[q * 4 + 3] = u.w;
        }
        sb1 = span_b[j1];
        if (j2ok) sb2 = span_b[j2];
        { int g = j1 / 49, q = j1 % 49; goff1 = g * 56 + (q / 7) * 8 + (q % 7); }
        if (j2ok) { int g = j2 / 49, q = j2 % 49; goff2 = g * 56 + (q / 7) * 8 + (q % 7); }
    }

    // ---- stage x tile via cp.async.bulk ----
    bool edge = (x0 < 0) || (x0 + 13 > 129) || (y0 < 0) || (y0 + 13 > 129);
    if (tid == 0) mbar_init(mbar, 1);
    if (edge) {
        for (int i = tid; i < TS * TS * 16; i += 512)
            *(float4*)&xs[i * 4] = make_float4(0.f, 0.f, 0.f, 0.f);
    }
    pdl_wait();
    __syncthreads();
    if (tid == 0) {
        if (edge)
            asm volatile("fence.proxy.async.shared::cta;" ::: "memory");
        int sx = x0 < 0 ? 0 : x0;
        int ex = x0 + 13 > 129 ? 129 : x0 + 13;
        uint32_t cnt_bytes = (uint32_t)(ex - sx + 1) * 256u;
        uint32_t dxoff = (uint32_t)(sx - x0) * 256u;
        uint32_t total = 0;
#pragma unroll
        for (int row = 0; row < TS; row++) {
            int yy = y0 + row;
            if (yy >= 0 && yy < XH) total += cnt_bytes;
        }
        mbar_expect_tx(mbar, total);
#pragma unroll
        for (int row = 0; row < TS; row++) {
            int yy = y0 + row;
            if (yy >= 0 && yy < XH)
                bulk_g2s(smem_base + (uint32_t)(row * TS) * 256u + dxoff,
                         xin + (yy * XW + sx) * XC, cnt_bytes, mbar);
        }
    }
    if (tid < 256) *(float4*)&redT_s[tid * 4] = *(const float4*)&redT4[tid * 4];
    if (tid < 16) beta_s[tid] = beta[tid];
    __syncthreads();          // redT/beta visible
    mbar_wait(mbar, 0);       // x tile complete (acquire)

    // ---- T phase (ALL 16 warps): lane = 1 r x 2 adjacent px ----
    {
        int r = tid & 15, pg = tid >> 4;      // pg = pair 0..31
        int p0 = pg * 2;
        int py = p0 >> 3, pxx = p0 & 7;       // p0 even -> p0+1 same row
        const float* xp = &xs[((py + 3) * TS + (pxx + 3)) * XC];
        float a0 = 0.f, a1 = 0.f;
#pragma unroll
        for (int q = 0; q < 16; q++) {
            float4 wv = *(const float4*)&redT_s[(q * 16 + r) * 4];
            float4 xA = *(const float4*)&xp[q * 4];
            float4 xB = *(const float4*)&xp[XC + q * 4];
            a0 = fmaf(wv.x, xA.x, a0); a0 = fmaf(wv.y, xA.y, a0);
            a0 = fmaf(wv.z, xA.z, a0); a0 = fmaf(wv.w, xA.w, a0);
            a1 = fmaf(wv.x, xB.x, a1); a1 = fmaf(wv.y, xB.y, a1);
            a1 = fmaf(wv.z, xB.z, a1); a1 = fmaf(wv.w, xB.w, a1);
        }
        float bv = beta_s[r];
        float2 v = make_float2(fmaxf(a0 + bv, 0.f), fmaxf(a1 + bv, 0.f));
        *(float2*)&t2_s[pg * 32 + r * 2] = v;
    }
    __syncthreads();   // t done; redT_s dead -> sker writable

    // ---- K phase (ALL 16 warps): 8 pairs each, 2 j per lane ----
    {
#pragma unroll 1
        for (int p = 0; p < 8; p++) {
            int pair = kpbase + p;
            const ulonglong2* tp2 = (const ulonglong2*)&t2_s[pair * 32];
            unsigned long long a1 = dup2(sb1), a2 = dup2(sb2);
#pragma unroll
            for (int i = 0; i < 8; i++) {
                ulonglong2 tv = tp2[i];
                a1 = fma2(dup2(wr1[2 * i]),     tv.x, a1);
                a1 = fma2(dup2(wr1[2 * i + 1]), tv.y, a1);
                a2 = fma2(dup2(wr2[2 * i]),     tv.x, a2);
                a2 = fma2(dup2(wr2[2 * i + 1]), tv.y, a2);
            }
            float2 k1 = unpack2(a1);
            sker[(pair * 2) * 224 + goff1]     = k1.x;
            sker[(pair * 2 + 1) * 224 + goff1] = k1.y;
            if (j2ok) {
                float2 k2 = unpack2(a2);
                sker[(pair * 2) * 224 + goff2]     = k2.x;
                sker[(pair * 2 + 1) * 224 + goff2] = k2.y;
            }
        }
    }
    __syncthreads();

    // ---- A phase (ALL 16 warps): warp tile 2 wide x 2 tall (4 px), 2 ch/lane ----
    {
        int px0 = (w & 3) * 2, py0 = (w >> 2) * 2;
        int g = lane >> 3;
        int c0 = lane * 2;
        float2 a[2][2];
#pragma unroll
        for (int r = 0; r < 2; r++)
#pragma unroll
            for (int c = 0; c < 2; c++) a[r][c] = make_float2(0.f, 0.f);

#pragma unroll
        for (int dya = 0; dya < 8; dya++) {
            float2 xr[8];
            const float* row = &xs[((py0 + dya) * TS + px0) * XC + c0];
#pragma unroll
            for (int dx = 0; dx < 8; dx++)
                xr[dx] = *(const float2*)&row[dx * XC];
#pragma unroll
            for (int r = 0; r < 2; r++) {
                int dy = dya - r;
                if (dy < 0 || dy > 6) continue;
#pragma unroll
                for (int c = 0; c < 2; c++) {
                    int pl = (py0 + r) * 8 + (px0 + c);
                    const float4* kp = (const float4*)&sker[(pl * 4 + g) * 56 + dy * 8];
                    float4 ka = kp[0], kb = kp[1];
                    a[r][c].x = fmaf(ka.x, xr[c + 0].x, a[r][c].x);
                    a[r][c].y = fmaf(ka.x, xr[c + 0].y, a[r][c].y);
                    a[r][c].x = fmaf(ka.y, xr[c + 1].x, a[r][c].x);
                    a[r][c].y = fmaf(ka.y, xr[c + 1].y, a[r][c].y);
                    a[r][c].x = fmaf(ka.z, xr[c + 2].x, a[r][c].x);
                    a[r][c].y = fmaf(ka.z, xr[c + 2].y, a[r][c].y);
                    a[r][c].x = fmaf(ka.w, xr[c + 3].x, a[r][c].x);
                    a[r][c].y = fmaf(ka.w, xr[c + 3].y, a[r][c].y);
                    a[r][c].x = fmaf(kb.x, xr[c + 4].x, a[r][c].x);
                    a[r][c].y = fmaf(kb.x, xr[c + 4].y, a[r][c].y);
                    a[r][c].x = fmaf(kb.y, xr[c + 5].x, a[r][c].x);
                    a[r][c].y = fmaf(kb.y, xr[c + 5].y, a[r][c].y);
                    a[r][c].x = fmaf(kb.z, xr[c + 6].x, a[r][c].x);
                    a[r][c].y = fmaf(kb.z, xr[c + 6].y, a[r][c].y);
                }
            }
        }
#pragma unroll
        for (int r = 0; r < 2; r++)
#pragma unroll
            for (int c = 0; c < 2; c++) {
                int gy = by * TILE + py0 + r;
                int gx = bx * TILE + px0 + c;
                if (gy < XH && gx < XW) {
                    float2 o = make_float2(fmaxf(a[r][c].x, 0.f), fmaxf(a[r][c].y, 0.f));
                    *(float2*)&xout[(gy * XW + gx) * XC + c0] = o;
                }
            }
    }
    pdl_trigger();
}

// ---------------- conv_out: tiled (8x8), pair-blocked, bulk-staged ----------------
#define CO_XT   0
#define CO_WS   6400
#define CO_BS   (CO_WS + 6912)     // 13312
#define CO_MBAR (CO_BS + 12)       // 13324
#define CO_TOT  (CO_MBAR + 2)      // 13326 floats = 53,304 B

__global__ void __launch_bounds__(256)
conv_out_kernel(const float* __restrict__ x,
                const float* __restrict__ w,
                const float* __restrict__ b,
                float* __restrict__ out) {
    extern __shared__ float cs[];
    float* xt = cs + CO_XT;
    float* wS = cs + CO_WS;
    float* bS = cs + CO_BS;
    uint32_t smem_base = smem_u32(cs);
    uint32_t mbar = smem_base + CO_MBAR * 4;

    int tid = threadIdx.x, lane = tid & 31, wp = tid >> 5;
    int by = blockIdx.x >> 4, bx = blockIdx.x & 15;
    int y0 = by * 8, x0 = bx * 8;

    if (tid == 0) mbar_init(mbar, 1);
    for (int i = tid; i < 9 * 12 * 64; i += 256) {
        int c = i & 63;
        int rest = i >> 6;
        int oc = rest % 12, tap = rest / 12;
        wS[(tap * 12 + oc) * 64 + c] = w[(oc * 64 + c) * 9 + tap];
    }
    if (tid < 12) bS[tid] = b[tid];
    pdl_wait();
    __syncthreads();
    if (tid == 0) {
        mbar_expect_tx(mbar, 10 * 2560);
#pragma unroll
        for (int row = 0; row < 10; row++)
            bulk_g2s(smem_base + (uint32_t)(row * 640) * 4u,
                     x + ((y0 + row) * XW + x0) * XC, 2560, mbar);
    }
    __syncthreads();
    mbar_wait(mbar, 0);

    int c0 = lane * 2;
    int py = wp;
#pragma unroll
    for (int pair = 0; pair < 4; pair++) {
        int px0 = pair * 2;
        unsigned long long acc[2][12];
#pragma unroll
        for (int p = 0; p < 2; p++)
#pragma unroll
            for (int oc = 0; oc < 12; oc++) acc[p][oc] = 0ull;

#pragma unroll
        for (int ky = 0; ky < 3; ky++)
#pragma unroll
            for (int kx = 0; kx < 3; kx++) {
                int tap = ky * 3 + kx;
                unsigned long long wv[12];
#pragma unroll
                for (int oc = 0; oc < 12; oc++)
                    wv[oc] = *(const unsigned long long*)&wS[(tap * 12 + oc) * 64 + c0];
#pragma unroll
                for (int p = 0; p < 2; p++) {
                    unsigned long long xv = *(const unsigned long long*)
                        &xt[((py + ky) * 10 + (px0 + p + kx)) * 64 + c0];
#pragma unroll
                    for (int oc = 0; oc < 12; oc++)
                        acc[p][oc] = fma2(wv[oc], xv, acc[p][oc]);
                }
            }

#pragma unroll
        for (int p = 0; p < 2; p++) {
            float o[12];
#pragma unroll
            for (int oc = 0; oc < 12; oc++) {
                float2 v = unpack2(acc[p][oc]);
                o[oc] = v.x + v.y;
#pragma unroll
                for (int s = 16; s > 0; s >>= 1)
                    o[oc] += __shfl_xor_sync(0xffffffffu, o[oc], s);
            }
            if (lane == 0) {
                int gy = y0 + py, gx = x0 + px0 + p;
#pragma unroll
                for (int oc = 0; oc < 12; oc++) {
                    int co = oc >> 2, rem = oc & 3;
                    int dy = rem >> 1, dx = rem & 1;
                    out[(co * 256 + (2 * gy + dy)) * 256 + (2 * gx + dx)] = o[oc] + bS[oc];
                }
            }
        }
    }
}

// ---------------- launch ----------------
extern "C" void kernel_launch(void* const* d_in, const int* in_sizes, int n_in,
                              void* d_out, int out_size) {
    const float* input      = (const float*)d_in[0];
    const float* conv_in_w  = (const float*)d_in[1];
    const float* conv_in_b  = (const float*)d_in[2];
    const float* red_w      = (const float*)d_in[3];
    const float* bn_gamma   = (const float*)d_in[4];
    const float* bn_beta    = (const float*)d_in[5];
    const float* span_w     = (const float*)d_in[6];
    const float* span_b     = (const float*)d_in[7];
    const float* conv_out_w = (const float*)d_in[8];
    const float* conv_out_b = (const float*)d_in[9];
    float* out = (float*)d_out;

    float *bufA, *bufB, *redT;
    cudaGetSymbolAddress((void**)&bufA, g_bufA);
    cudaGetSymbolAddress((void**)&bufB, g_bufB);
    cudaGetSymbolAddress((void**)&redT, g_redT);

    const int SMEM_INV = SM_TOT * 4;   // 111,688 B
    const int SMEM_CO  = CO_TOT * 4;   // 53,304 B
    cudaFuncSetAttribute(inv_kernel, cudaFuncAttributeMaxDynamicSharedMemorySize, SMEM_INV);
    cudaFuncSetAttribute(conv_out_kernel, cudaFuncAttributeMaxDynamicSharedMemorySize, SMEM_CO);

    conv_in_kernel<<<NTB * NTB + 24, 256>>>(input, conv_in_w, conv_in_b,
                                            red_w, bn_gamma, bufA);

    cudaLaunchAttribute pdl_attr;
    pdl_attr.id = cudaLaunchAttributeProgrammaticStreamSerialization;
    pdl_attr.val.programmaticStreamSerializationAllowed = 1;

    for (int l = 0; l < NLAYERS; l++) {
        const float* src = (l & 1) ? bufB : bufA;
        float* dst       = (l & 1) ? bufA : bufB;
        cudaLaunchConfig_t cfg = {};
        cfg.gridDim = dim3(NTB * NTB, 1, 1);
        cfg.blockDim = dim3(512, 1, 1);
        cfg.dynamicSmemBytes = SMEM_INV;
        cfg.attrs = &pdl_attr;
        cfg.numAttrs = 1;
        cudaLaunchKernelEx(&cfg, inv_kernel,
                           src, dst,
                           (const float*)(redT + l * 1024),
                           (const float*)(bn_beta + l * 16),
                           (const float*)(span_w + l * NSPAN * NRED),
                           (const float*)(span_b + l * NSPAN));
    }

    {
        cudaLaunchConfig_t cfg = {};
        cfg.gridDim = dim3(256, 1, 1);
        cfg.blockDim = dim3(256, 1, 1);
        cfg.dynamicSmemBytes = SMEM_CO;
        cfg.attrs = &pdl_attr;
        cfg.numAttrs = 1;
        cudaLaunchKernelEx(&cfg, conv_out_kernel,
                           (const float*)bufA, conv_out_w, conv_out_b, out);
    }
}

// round 15
// speedup vs baseline: 1.0298x; 1.0298x over previous
#include <cuda_runtime.h>
#include <cstdint>

#define XH 130
#define XW 130
#define XC 64
#define NPIX (XH * XW)
#define NRED 16
#define NSPAN 196
#define NLAYERS 6
#define TILE 8
#define TS 14
#define NTB 17

// ---------------- scratch ----------------
__device__ float g_bufA[NPIX * XC];
__device__ float g_bufB[NPIX * XC];
__device__ float g_redT[NLAYERS][16 * 16 * 4];   // [q][r] float4 (gamma-folded)

// ---------------- f32x2 helpers ----------------
__device__ __forceinline__ unsigned long long dup2(float k) {
    unsigned long long r;
    asm("mov.b64 %0, {%1, %1};" : "=l"(r) : "f"(k));
    return r;
}
__device__ __forceinline__ unsigned long long pack2f(float2 v) {
    unsigned long long r;
    asm("mov.b64 %0, {%1, %2};" : "=l"(r) : "f"(v.x), "f"(v.y));
    return r;
}
__device__ __forceinline__ unsigned long long fma2(unsigned long long a,
                                                   unsigned long long b,
                                                   unsigned long long c) {
    unsigned long long d;
    asm("fma.rn.f32x2 %0, %1, %2, %3;" : "=l"(d) : "l"(a), "l"(b), "l"(c));
    return d;
}
__device__ __forceinline__ float2 unpack2(unsigned long long v) {
    float2 r;
    asm("mov.b64 {%0, %1}, %2;" : "=f"(r.x), "=f"(r.y) : "l"(v));
    return r;
}

// ---------------- PDL helpers ----------------
__device__ __forceinline__ void pdl_wait() {
    asm volatile("griddepcontrol.wait;" ::: "memory");
}
__device__ __forceinline__ void pdl_trigger() {
    asm volatile("griddepcontrol.launch_dependents;" ::: "memory");
}

// ---------------- async-bulk helpers ----------------
__device__ __forceinline__ uint32_t smem_u32(const void* p) {
    uint32_t a;
    asm("{ .reg .u64 t; cvta.to.shared.u64 t, %1; cvt.u32.u64 %0, t; }"
        : "=r"(a) : "l"(p));
    return a;
}
__device__ __forceinline__ void mbar_init(uint32_t addr, uint32_t cnt) {
    asm volatile("mbarrier.init.shared.b64 [%0], %1;" :: "r"(addr), "r"(cnt) : "memory");
}
__device__ __forceinline__ void mbar_expect_tx(uint32_t addr, uint32_t bytes) {
    asm volatile("mbarrier.arrive.expect_tx.shared.b64 _, [%0], %1;"
                 :: "r"(addr), "r"(bytes) : "memory");
}
__device__ __forceinline__ void bulk_g2s(uint32_t dst, const void* src,
                                         uint32_t bytes, uint32_t mbar) {
    asm volatile("cp.async.bulk.shared::cta.global.mbarrier::complete_tx::bytes "
                 "[%0], [%1], %2, [%3];"
                 :: "r"(dst), "l"(src), "r"(bytes), "r"(mbar) : "memory");
}
__device__ __forceinline__ void mbar_wait(uint32_t addr, uint32_t parity) {
    asm volatile(
        "{\n\t.reg .pred P;\n\t"
        "W_%=:\n\t"
        "mbarrier.try_wait.parity.acquire.cta.shared::cta.b64 P, [%0], %1, 0x989680;\n\t"
        "@P bra.uni D_%=;\n\t"
        "bra.uni W_%=;\n\t"
        "D_%=:\n\t}"
        :: "r"(addr), "r"(parity) : "memory");
}

// ---------------- conv_in: tiled (8x8 px/block), weights in registers ----------------
__global__ void conv_in_kernel(const float* __restrict__ in,
                               const float* __restrict__ w,
                               const float* __restrict__ b,
                               const float* __restrict__ red_w,
                               const float* __restrict__ gamma,
                               float* __restrict__ out) {
    if (blockIdx.x >= NTB * NTB) {
        int idx = (blockIdx.x - NTB * NTB) * 256 + threadIdx.x;   // 0..6143
        int l = idx >> 10, rem = idx & 1023;
        int r = rem >> 6, c = rem & 63;
        g_redT[l][((c >> 2) * 16 + r) * 4 + (c & 3)] =
            gamma[l * 16 + r] * red_w[(l * 16 + r) * 64 + c];
        pdl_trigger();
        return;
    }
    __shared__ float ws[27 * 64];
    __shared__ float xt[3 * 10 * 10];
    int tid = threadIdx.x, lane = tid & 31, wp = tid >> 5;
    int by = blockIdx.x / NTB, bx = blockIdx.x % NTB;
    int y0 = by * TILE, x0 = bx * TILE;

    for (int i = tid; i < 27 * 64; i += 256) {
        int t = i >> 6, c = i & 63;
        ws[t * 64 + c] = w[c * 27 + t];
    }
    for (int i = tid; i < 300; i += 256) {
        int ic = i / 100, rem = i % 100;
        int rr = rem / 10, cc = rem % 10;
        int gy = y0 - 2 + rr, gx = x0 - 2 + cc;
        float v = 0.f;
        if (gy >= 0 && gy < 128 && gx >= 0 && gx < 128)
            v = in[(ic * 128 + gy) * 128 + gx];
        xt[i] = v;
    }
    __syncthreads();

    int c0 = lane * 2;
    unsigned long long wv[27];
#pragma unroll
    for (int t = 0; t < 27; t++)
        wv[t] = pack2f(*(const float2*)&ws[t * 64 + c0]);
    unsigned long long bv = pack2f(make_float2(b[c0], b[c0 + 1]));

#pragma unroll
    for (int k = 0; k < 8; k++) {
        int pp = wp * 8 + k;
        int py = pp >> 3, px = pp & 7;
        int gy = y0 + py, gx = x0 + px;
        unsigned long long acc = bv;
#pragma unroll
        for (int ic = 0; ic < 3; ic++)
#pragma unroll
            for (int ky = 0; ky < 3; ky++)
#pragma unroll
                for (int kx = 0; kx < 3; kx++) {
                    float xv = xt[(ic * 10 + (py + ky)) * 10 + (px + kx)];
                    acc = fma2(wv[ic * 9 + ky * 3 + kx], dup2(xv), acc);
                }
        if (gy < XH && gx < XW) {
            float2 o = unpack2(acc);
            *(float2*)&out[(gy * XW + gx) * XC + c0] = o;
        }
    }
    pdl_trigger();
}

// ---------------- fused involution layer ----------------
#define SM_XS   0
#define SM_SKER (TS * TS * XC)                // 12544
#define SM_T2   (SM_SKER + 64 * 224)          // 26880
#define SM_BETA (SM_T2 + 1024)                // 27904
#define SM_MBAR (SM_BETA + 16)                // 27920 (8B aligned)
#define SM_TOT  (SM_MBAR + 2)                 // 27922 floats = 111,688 B

__global__ void __launch_bounds__(512, 2)
inv_kernel(const float* __restrict__ xin, float* __restrict__ xout,
           const float* __restrict__ redT4, const float* __restrict__ beta,
           const float* __restrict__ span_w, const float* __restrict__ span_b) {
    extern __shared__ float sm[];
    float* xs     = sm + SM_XS;
    float* sker   = sm + SM_SKER;
    float* redT_s = sker;            // alias: read in T phase, overwritten in K phase
    float* t2_s   = sm + SM_T2;
    float* beta_s = sm + SM_BETA;

    int tid = threadIdx.x, lane = tid & 31, w = tid >> 5;
    int by = blockIdx.x / NTB, bx = blockIdx.x % NTB;
    int y0 = by * TILE - 3, x0 = bx * TILE - 3;

    uint32_t smem_base = smem_u32(sm);
    uint32_t mbar = smem_base + SM_MBAR * 4;

    // ---- PDL prologue: span weights (pure inputs) ----
    float wr1[16], wr2[16], sb1 = 0.f, sb2 = 0.f;
    int goff1 = 0, goff2 = 0;
    int kpbase = (w >> 2) * 8;
    bool j2ok;
    {
        int j1 = (w & 3) * 32 + lane;
        int j2 = j1 + 128;
        j2ok = (j2 < NSPAN);
#pragma unroll
        for (int q = 0; q < 4; q++) {
            float4 v = *(const float4*)&span_w[j1 * 16 + q * 4];
            wr1[q * 4] = v.x; wr1[q * 4 + 1] = v.y; wr1[q * 4 + 2] = v.z; wr1[q * 4 + 3] = v.w;
            float4 u = make_float4(0.f, 0.f, 0.f, 0.f);
            if (j2ok) u = *(const float4*)&span_w[j2 * 16 + q * 4];
            wr2[q * 4] = u.x; wr2[q * 4 + 1] = u.y; wr2[q * 4 + 2] = u.z; wr2[q * 4 + 3] = u.w;
        }
        sb1 = span_b[j1];
        if (j2ok) sb2 = span_b[j2];
        { int g = j1 / 49, q = j1 % 49; goff1 = g * 56 + (q / 7) * 8 + (q % 7); }
        if (j2ok) { int g = j2 / 49, q = j2 % 49; goff2 = g * 56 + (q / 7) * 8 + (q % 7); }
    }

    // ---- stage x tile via cp.async.bulk ----
    bool edge = (x0 < 0) || (x0 + 13 > 129) || (y0 < 0) || (y0 + 13 > 129);
    if (tid == 0) mbar_init(mbar, 1);
    if (edge) {
        for (int i = tid; i < TS * TS * 16; i += 512)
            *(float4*)&xs[i * 4] = make_float4(0.f, 0.f, 0.f, 0.f);
    }
    pdl_wait();
    __syncthreads();
    if (tid == 0) {
        if (edge)
            asm volatile("fence.proxy.async.shared::cta;" ::: "memory");
        int sx = x0 < 0 ? 0 : x0;
        int ex = x0 + 13 > 129 ? 129 : x0 + 13;
        uint32_t cnt_bytes = (uint32_t)(ex - sx + 1) * 256u;
        uint32_t dxoff = (uint32_t)(sx - x0) * 256u;
        uint32_t total = 0;
#pragma unroll
        for (int row = 0; row < TS; row++) {
            int yy = y0 + row;
            if (yy >= 0 && yy < XH) total += cnt_bytes;
        }
        mbar_expect_tx(mbar, total);
#pragma unroll
        for (int row = 0; row < TS; row++) {
            int yy = y0 + row;
            if (yy >= 0 && yy < XH)
                bulk_g2s(smem_base + (uint32_t)(row * TS) * 256u + dxoff,
                         xin + (yy * XW + sx) * XC, cnt_bytes, mbar);
        }
    }
    if (tid < 256) *(float4*)&redT_s[tid * 4] = *(const float4*)&redT4[tid * 4];
    if (tid < 16) beta_s[tid] = beta[tid];
    __syncthreads();          // redT/beta visible
    mbar_wait(mbar, 0);       // x tile complete (acquire)

    // ---- T phase (warps 0-3): lane = (rg 0..7, pg 0..15); 2 r x 4 px per lane ----
    if (w < 4) {
        int L = w * 32 + lane;            // 0..127
        int rg = L & 7, pg = L >> 3;
        int r0 = rg * 2;
        int px0 = pg * 4;
        int py = px0 >> 3, pxx = px0 & 7;
        const float* xp = &xs[((py + 3) * TS + (pxx + 3)) * XC];
        float acc[2][4];
#pragma unroll
        for (int a = 0; a < 2; a++)
#pragma unroll
            for (int i = 0; i < 4; i++) acc[a][i] = 0.f;
#pragma unroll
        for (int q = 0; q < 16; q++) {
            float4 w0 = *(const float4*)&redT_s[(q * 16 + r0) * 4];
            float4 w1 = *(const float4*)&redT_s[(q * 16 + r0 + 1) * 4];
#pragma unroll
            for (int i = 0; i < 4; i++) {
                float4 xv = *(const float4*)&xp[i * XC + q * 4];
                acc[0][i] = fmaf(w0.x, xv.x, acc[0][i]);
                acc[0][i] = fmaf(w0.y, xv.y, acc[0][i]);
                acc[0][i] = fmaf(w0.z, xv.z, acc[0][i]);
                acc[0][i] = fmaf(w0.w, xv.w, acc[0][i]);
                acc[1][i] = fmaf(w1.x, xv.x, acc[1][i]);
                acc[1][i] = fmaf(w1.y, xv.y, acc[1][i]);
                acc[1][i] = fmaf(w1.z, xv.z, acc[1][i]);
                acc[1][i] = fmaf(w1.w, xv.w, acc[1][i]);
            }
        }
#pragma unroll
        for (int a = 0; a < 2; a++) {
            int r = r0 + a;
            float bv = beta_s[r];
#pragma unroll
            for (int pj = 0; pj < 2; pj++) {
                int pair = pg * 2 + pj;
                float2 v = make_float2(fmaxf(acc[a][pj * 2] + bv, 0.f),
                                       fmaxf(acc[a][pj * 2 + 1] + bv, 0.f));
                *(float2*)&t2_s[pair * 32 + r * 2] = v;
            }
        }
    }
    __syncthreads();   // t done; redT_s dead -> sker writable

    // ---- K phase (ALL 16 warps): 8 pairs each, 2 j per lane, 2-pair interleave ----
    {
#pragma unroll 2
        for (int p = 0; p < 8; p++) {
            int pair = kpbase + p;
            const ulonglong2* tp2 = (const ulonglong2*)&t2_s[pair * 32];
            unsigned long long a1 = dup2(sb1), a2 = dup2(sb2);
#pragma unroll
            for (int i = 0; i < 8; i++) {
                ulonglong2 tv = tp2[i];
                a1 = fma2(dup2(wr1[2 * i]),     tv.x, a1);
                a1 = fma2(dup2(wr1[2 * i + 1]), tv.y, a1);
                a2 = fma2(dup2(wr2[2 * i]),     tv.x, a2);
                a2 = fma2(dup2(wr2[2 * i + 1]), tv.y, a2);
            }
            float2 k1 = unpack2(a1);
            sker[(pair * 2) * 224 + goff1]     = k1.x;
            sker[(pair * 2 + 1) * 224 + goff1] = k1.y;
            if (j2ok) {
                float2 k2 = unpack2(a2);
                sker[(pair * 2) * 224 + goff2]     = k2.x;
                sker[(pair * 2 + 1) * 224 + goff2] = k2.y;
            }
        }
    }
    __syncthreads();

    // ---- A phase (warps 0-7): warp tile 2 wide x 4 tall (8 px), 2 ch/lane ----
    if (w < 8) {
        int px0 = (w & 3) * 2, py0 = (w >> 2) * 4;
        int g = lane >> 3;
        int c0 = lane * 2;
        float2 a[4][2];
#pragma unroll
        for (int r = 0; r < 4; r++)
#pragma unroll
            for (int c = 0; c < 2; c++) a[r][c] = make_float2(0.f, 0.f);

#pragma unroll
        for (int dya = 0; dya < 10; dya++) {
            float2 xr[8];
            const float* row = &xs[((py0 + dya) * TS + px0) * XC + c0];
#pragma unroll
            for (int dx = 0; dx < 8; dx++)
                xr[dx] = *(const float2*)&row[dx * XC];
#pragma unroll
            for (int r = 0; r < 4; r++) {
                int dy = dya - r;
                if (dy < 0 || dy > 6) continue;
#pragma unroll
                for (int c = 0; c < 2; c++) {
                    int pl = (py0 + r) * 8 + (px0 + c);
                    const float4* kp = (const float4*)&sker[(pl * 4 + g) * 56 + dy * 8];
                    float4 ka = kp[0], kb = kp[1];
                    a[r][c].x = fmaf(ka.x, xr[c + 0].x, a[r][c].x);
                    a[r][c].y = fmaf(ka.x, xr[c + 0].y, a[r][c].y);
                    a[r][c].x = fmaf(ka.y, xr[c + 1].x, a[r][c].x);
                    a[r][c].y = fmaf(ka.y, xr[c + 1].y, a[r][c].y);
                    a[r][c].x = fmaf(ka.z, xr[c + 2].x, a[r][c].x);
                    a[r][c].y = fmaf(ka.z, xr[c + 2].y, a[r][c].y);
                    a[r][c].x = fmaf(ka.w, xr[c + 3].x, a[r][c].x);
                    a[r][c].y = fmaf(ka.w, xr[c + 3].y, a[r][c].y);
                    a[r][c].x = fmaf(kb.x, xr[c + 4].x, a[r][c].x);
                    a[r][c].y = fmaf(kb.x, xr[c + 4].y, a[r][c].y);
                    a[r][c].x = fmaf(kb.y, xr[c + 5].x, a[r][c].x);
                    a[r][c].y = fmaf(kb.y, xr[c + 5].y, a[r][c].y);
                    a[r][c].x = fmaf(kb.z, xr[c + 6].x, a[r][c].x);
                    a[r][c].y = fmaf(kb.z, xr[c + 6].y, a[r][c].y);
                }
            }
        }
#pragma unroll
        for (int r = 0; r < 4; r++)
#pragma unroll
            for (int c = 0; c < 2; c++) {
                int gy = by * TILE + py0 + r;
                int gx = bx * TILE + px0 + c;
                if (gy < XH && gx < XW) {
                    float2 o = make_float2(fmaxf(a[r][c].x, 0.f), fmaxf(a[r][c].y, 0.f));
                    *(float2*)&xout[(gy * XW + gx) * XC + c0] = o;
                }
            }
    }
    pdl_trigger();
}

// ---------------- conv_out: tiled (8x8), pair-blocked, bulk-staged ----------------
#define CO_XT   0
#define CO_WS   6400
#define CO_BS   (CO_WS + 6912)     // 13312
#define CO_MBAR (CO_BS + 12)       // 13324
#define CO_TOT  (CO_MBAR + 2)      // 13326 floats = 53,304 B

__global__ void __launch_bounds__(256)
conv_out_kernel(const float* __restrict__ x,
                const float* __restrict__ w,
                const float* __restrict__ b,
                float* __restrict__ out) {
    extern __shared__ float cs[];
    float* xt = cs + CO_XT;
    float* wS = cs + CO_WS;
    float* bS = cs + CO_BS;
    uint32_t smem_base = smem_u32(cs);
    uint32_t mbar = smem_base + CO_MBAR * 4;

    int tid = threadIdx.x, lane = tid & 31, wp = tid >> 5;
    int by = blockIdx.x >> 4, bx = blockIdx.x & 15;
    int y0 = by * 8, x0 = bx * 8;

    if (tid == 0) mbar_init(mbar, 1);
    for (int i = tid; i < 9 * 12 * 64; i += 256) {
        int c = i & 63;
        int rest = i >> 6;
        int oc = rest % 12, tap = rest / 12;
        wS[(tap * 12 + oc) * 64 + c] = w[(oc * 64 + c) * 9 + tap];
    }
    if (tid < 12) bS[tid] = b[tid];
    pdl_wait();
    __syncthreads();
    if (tid == 0) {
        mbar_expect_tx(mbar, 10 * 2560);
#pragma unroll
        for (int row = 0; row < 10; row++)
            bulk_g2s(smem_base + (uint32_t)(row * 640) * 4u,
                     x + ((y0 + row) * XW + x0) * XC, 2560, mbar);
    }
    __syncthreads();
    mbar_wait(mbar, 0);

    int c0 = lane * 2;
    int py = wp;
#pragma unroll
    for (int pair = 0; pair < 4; pair++) {
        int px0 = pair * 2;
        unsigned long long acc[2][12];
#pragma unroll
        for (int p = 0; p < 2; p++)
#pragma unroll
            for (int oc = 0; oc < 12; oc++) acc[p][oc] = 0ull;

#pragma unroll
        for (int ky = 0; ky < 3; ky++)
#pragma unroll
            for (int kx = 0; kx < 3; kx++) {
                int tap = ky * 3 + kx;
                unsigned long long wv[12];
#pragma unroll
                for (int oc = 0; oc < 12; oc++)
                    wv[oc] = *(const unsigned long long*)&wS[(tap * 12 + oc) * 64 + c0];
#pragma unroll
                for (int p = 0; p < 2; p++) {
                    unsigned long long xv = *(const unsigned long long*)
                        &xt[((py + ky) * 10 + (px0 + p + kx)) * 64 + c0];
#pragma unroll
                    for (int oc = 0; oc < 12; oc++)
                        acc[p][oc] = fma2(wv[oc], xv, acc[p][oc]);
                }
            }

#pragma unroll
        for (int p = 0; p < 2; p++) {
            float o[12];
#pragma unroll
            for (int oc = 0; oc < 12; oc++) {
                float2 v = unpack2(acc[p][oc]);
                o[oc] = v.x + v.y;
#pragma unroll
                for (int s = 16; s > 0; s >>= 1)
                    o[oc] += __shfl_xor_sync(0xffffffffu, o[oc], s);
            }
            if (lane == 0) {
                int gy = y0 + py, gx = x0 + px0 + p;
#pragma unroll
                for (int oc = 0; oc < 12; oc++) {
                    int co = oc >> 2, rem = oc & 3;
                    int dy = rem >> 1, dx = rem & 1;
                    out[(co * 256 + (2 * gy + dy)) * 256 + (2 * gx + dx)] = o[oc] + bS[oc];
                }
            }
        }
    }
}

// ---------------- launch ----------------
extern "C" void kernel_launch(void* const* d_in, const int* in_sizes, int n_in,
                              void* d_out, int out_size) {
    const float* input      = (const float*)d_in[0];
    const float* conv_in_w  = (const float*)d_in[1];
    const float* conv_in_b  = (const float*)d_in[2];
    const float* red_w      = (const float*)d_in[3];
    const float* bn_gamma   = (const float*)d_in[4];
    const float* bn_beta    = (const float*)d_in[5];
    const float* span_w     = (const float*)d_in[6];
    const float* span_b     = (const float*)d_in[7];
    const float* conv_out_w = (const float*)d_in[8];
    const float* conv_out_b = (const float*)d_in[9];
    float* out = (float*)d_out;

    float *bufA, *bufB, *redT;
    cudaGetSymbolAddress((void**)&bufA, g_bufA);
    cudaGetSymbolAddress((void**)&bufB, g_bufB);
    cudaGetSymbolAddress((void**)&redT, g_redT);

    const int SMEM_INV = SM_TOT * 4;   // 111,688 B
    const int SMEM_CO  = CO_TOT * 4;   // 53,304 B
    cudaFuncSetAttribute(inv_kernel, cudaFuncAttributeMaxDynamicSharedMemorySize, SMEM_INV);
    cudaFuncSetAttribute(conv_out_kernel, cudaFuncAttributeMaxDynamicSharedMemorySize, SMEM_CO);

    conv_in_kernel<<<NTB * NTB + 24, 256>>>(input, conv_in_w, conv_in_b,
                                            red_w, bn_gamma, bufA);

    cudaLaunchAttribute pdl_attr;
    pdl_attr.id = cudaLaunchAttributeProgrammaticStreamSerialization;
    pdl_attr.val.programmaticStreamSerializationAllowed = 1;

    for (int l = 0; l < NLAYERS; l++) {
        const float* src = (l & 1) ? bufB : bufA;
        float* dst       = (l & 1) ? bufA : bufB;
        cudaLaunchConfig_t cfg = {};
        cfg.gridDim = dim3(NTB * NTB, 1, 1);
        cfg.blockDim = dim3(512, 1, 1);
        cfg.dynamicSmemBytes = SMEM_INV;
        cfg.attrs = &pdl_attr;
        cfg.numAttrs = 1;
        cudaLaunchKernelEx(&cfg, inv_kernel,
                           src, dst,
                           (const float*)(redT + l * 1024),
                           (const float*)(bn_beta + l * 16),
                           (const float*)(span_w + l * NSPAN * NRED),
                           (const float*)(span_b + l * NSPAN));
    }

    {
        cudaLaunchConfig_t cfg = {};
        cfg.gridDim = dim3(256, 1, 1);
        cfg.blockDim = dim3(256, 1, 1);
        cfg.dynamicSmemBytes = SMEM_CO;
        cfg.attrs = &pdl_attr;
        cfg.numAttrs = 1;
        cudaLaunchKernelEx(&cfg, conv_out_kernel,
                           (const float*)bufA, conv_out_w, conv_out_b, out);
    }
}